// round 15
// baseline (speedup 1.0000x reference)
#include <cuda_runtime.h>
#include <cuda_bf16.h>
#include <math.h>
#include <stdint.h>

#define D_MODEL 1024
#define N_PATCH 1024
#define M_ROWS 4096
#define D_FF 2048
#define E_LAYERS 8
#define P_LEN 96
#define PE_COEF (-0.0089944730195079915f)
#define ATTN_SCALE 0.08838834764831845f
#define WSZ (E_LAYERS * D_MODEL * D_MODEL)
#define WFF (E_LAYERS * D_FF * D_MODEL)

__device__ float g_h  [M_ROWS * D_MODEL];
__device__ float g_tmp[M_ROWS * D_MODEL];
__device__ __nv_bfloat16 g_h_hi[M_ROWS*D_MODEL], g_h_lo[M_ROWS*D_MODEL];
__device__ __nv_bfloat16 g_q_hi[M_ROWS*D_MODEL], g_q_lo[M_ROWS*D_MODEL];
__device__ __nv_bfloat16 g_k_hi[M_ROWS*D_MODEL], g_k_lo[M_ROWS*D_MODEL];
__device__ __nv_bfloat16 g_v_hi[M_ROWS*D_MODEL], g_v_lo[M_ROWS*D_MODEL];
__device__ __nv_bfloat16 g_att_hi[M_ROWS*D_MODEL], g_att_lo[M_ROWS*D_MODEL];
__device__ __nv_bfloat16 g_ff_hi[M_ROWS*D_FF], g_ff_lo[M_ROWS*D_FF];
__device__ __nv_bfloat16 g_wqkv_hi[3 * WSZ], g_wqkv_lo[3 * WSZ];
__device__ __nv_bfloat16 g_wo_hi[WSZ], g_wo_lo[WSZ];
__device__ __nv_bfloat16 g_w1_hi[WFF], g_w1_lo[WFF];
__device__ __nv_bfloat16 g_w2_hi[WFF], g_w2_lo[WFF];
__device__ __nv_bfloat16 g_wp_hi[P_LEN*D_MODEL], g_wp_lo[P_LEN*D_MODEL];

__device__ __forceinline__ uint32_t smem_u32(const void* p) {
    uint32_t a;
    asm("{ .reg .u64 t; cvta.to.shared.u64 t, %1; cvt.u32.u64 %0, t; }" : "=r"(a) : "l"(p));
    return a;
}
__device__ __forceinline__ void cpasync16(uint32_t d, const void* s) {
    asm volatile("cp.async.cg.shared.global [%0], [%1], 16;" :: "r"(d), "l"(s) : "memory");
}
__device__ __forceinline__ void cpasync16z(uint32_t d, const void* s, int sz) {
    asm volatile("cp.async.cg.shared.global [%0], [%1], 16, %2;" :: "r"(d), "l"(s), "r"(sz) : "memory");
}
__device__ __forceinline__ void cp_commit(){ asm volatile("cp.async.commit_group;":::"memory"); }
__device__ __forceinline__ void cp_wait1(){ asm volatile("cp.async.wait_group 1;":::"memory"); }
__device__ __forceinline__ void cp_wait0(){ asm volatile("cp.async.wait_group 0;":::"memory"); }
__device__ __forceinline__ void ldsm4(uint32_t* r, uint32_t a) {
    asm volatile("ldmatrix.sync.aligned.m8n8.x4.shared.b16 {%0,%1,%2,%3}, [%4];"
                 : "=r"(r[0]), "=r"(r[1]), "=r"(r[2]), "=r"(r[3]) : "r"(a));
}
__device__ __forceinline__ void ldsm4t(uint32_t* r, uint32_t a) {
    asm volatile("ldmatrix.sync.aligned.m8n8.x4.trans.shared.b16 {%0,%1,%2,%3}, [%4];"
                 : "=r"(r[0]), "=r"(r[1]), "=r"(r[2]), "=r"(r[3]) : "r"(a));
}
__device__ __forceinline__ void mma16816(float* d, const uint32_t* a, const uint32_t* b) {
    asm volatile("mma.sync.aligned.m16n8k16.row.col.f32.bf16.bf16.f32 "
        "{%0,%1,%2,%3}, {%4,%5,%6,%7}, {%8,%9}, {%0,%1,%2,%3};"
        : "+f"(d[0]), "+f"(d[1]), "+f"(d[2]), "+f"(d[3])
        : "r"(a[0]), "r"(a[1]), "r"(a[2]), "r"(a[3]), "r"(b[0]), "r"(b[1]));
}
__device__ __forceinline__ void split2(float v0, float v1, __nv_bfloat162* hi, __nv_bfloat162* lo) {
    __nv_bfloat16 h0 = __float2bfloat16_rn(v0), h1 = __float2bfloat16_rn(v1);
    lo->x = __float2bfloat16_rn(v0 - __bfloat162float(h0));
    lo->y = __float2bfloat16_rn(v1 - __bfloat162float(h1));
    hi->x = h0; hi->y = h1;
}
__device__ __forceinline__ void split2u(float v0, float v1, uint32_t* hi, uint32_t* lo) {
    __nv_bfloat162 h, l;
    split2(v0, v1, &h, &l);
    *hi = *reinterpret_cast<uint32_t*>(&h);
    *lo = *reinterpret_cast<uint32_t*>(&l);
}

// ======================= weight converters ==================================
__global__ void __launch_bounds__(256) cvt_pair_kernel(
    const float* __restrict__ w, __nv_bfloat16* __restrict__ hi,
    __nv_bfloat16* __restrict__ lo, int n4)
{
    int i = blockIdx.x * 256 + threadIdx.x;
    if (i >= n4) return;
    float4 x = ((const float4*)w)[i];
    __nv_bfloat162 h0, l0, h1, l1;
    split2(x.x, x.y, &h0, &l0);
    split2(x.z, x.w, &h1, &l1);
    ((__nv_bfloat162*)hi)[i*2+0] = h0; ((__nv_bfloat162*)hi)[i*2+1] = h1;
    ((__nv_bfloat162*)lo)[i*2+0] = l0; ((__nv_bfloat162*)lo)[i*2+1] = l1;
}

__global__ void __launch_bounds__(256) cvt3_kernel(
    const float* __restrict__ w0, const float* __restrict__ w1,
    const float* __restrict__ w2,
    __nv_bfloat16* __restrict__ hi, __nv_bfloat16* __restrict__ lo)
{
    const int sel = blockIdx.y;
    const float* w = (sel == 0) ? w0 : (sel == 1) ? w1 : w2;
    int i = blockIdx.x * 256 + threadIdx.x;
    float4 x = ((const float4*)w)[i];
    size_t base = (size_t)sel * (WSZ / 2);
    __nv_bfloat162 h0, l0, h1, l1;
    split2(x.x, x.y, &h0, &l0);
    split2(x.z, x.w, &h1, &l1);
    ((__nv_bfloat162*)hi)[base + i*2+0] = h0;
    ((__nv_bfloat162*)hi)[base + i*2+1] = h1;
    ((__nv_bfloat162*)lo)[base + i*2+0] = l0;
    ((__nv_bfloat162*)lo)[base + i*2+1] = l1;
}

// ======================= bf16x3 GEMM core ====================================
#define GSTG 32768
#define GSMEM (3 * GSTG)

template <bool MASKED>
__device__ __forceinline__ void g_load_stage(
    uint32_t sb, const __nv_bfloat16* Ahi, const __nv_bfloat16* Alo,
    const __nv_bfloat16* Bhi, const __nv_bfloat16* Blo,
    int row0, int col0, int kt, int K, int nValid, int tid)
{
#pragma unroll
    for (int i = 0; i < 2; i++) {
        int idx = tid + i * 256;
        int r = idx >> 2, c = idx & 3;
        uint32_t so = (uint32_t)(r * 64 + ((c ^ ((r >> 1) & 3)) * 16));
        size_t aoff = (size_t)(row0 + r) * K + kt * 32 + c * 8;
        cpasync16(sb + so,        Ahi + aoff);
        cpasync16(sb + 8192 + so, Alo + aoff);
        if (MASKED) {
            int br = col0 + r;
            int sz = (br < nValid) ? 16 : 0;
            if (br >= nValid) br = nValid - 1;
            size_t boff = (size_t)br * K + kt * 32 + c * 8;
            cpasync16z(sb + 16384 + so, Bhi + boff, sz);
            cpasync16z(sb + 24576 + so, Blo + boff, sz);
        } else {
            size_t boff = (size_t)(col0 + r) * K + kt * 32 + c * 8;
            cpasync16(sb + 16384 + so, Bhi + boff);
            cpasync16(sb + 24576 + so, Blo + boff);
        }
    }
}

template <bool MASKED>
__device__ __forceinline__ void gemm_core(
    uint32_t smb, const __nv_bfloat16* Ahi, const __nv_bfloat16* Alo,
    const __nv_bfloat16* Bhi, const __nv_bfloat16* Blo,
    const float* bias,
    const __nv_bfloat16* resHi, const __nv_bfloat16* resLo,
    float* Cf, __nv_bfloat16* Chi, __nv_bfloat16* Clo,
    int K, int ldC, int nValid, int relu, int row0, int col0)
{
    const int tid = threadIdx.x, lane = tid & 31, warp = tid >> 5;
    const int warpM = warp >> 2, warpN = warp & 3;
    const int sub = lane & 7, tile = lane >> 3;
    const int xorv = (sub >> 1) & 3;
    const int aRow = warpM * 64 + (tile & 1) * 8 + sub;
    const int aKch = tile >> 1;
    const int bRow = warpN * 32 + (tile >> 1) * 8 + sub;
    const int bKch = tile & 1;

    float acc[4][4][4];
#pragma unroll
    for (int mt = 0; mt < 4; mt++)
#pragma unroll
        for (int nt = 0; nt < 4; nt++)
#pragma unroll
            for (int e = 0; e < 4; e++) acc[mt][nt][e] = 0.f;

    const int Kt = K >> 5;
    g_load_stage<MASKED>(smb, Ahi, Alo, Bhi, Blo, row0, col0, 0, K, nValid, tid);
    cp_commit();
    g_load_stage<MASKED>(smb + GSTG, Ahi, Alo, Bhi, Blo, row0, col0, 1, K, nValid, tid);
    cp_commit();

    for (int it = 0; it < Kt; it++) {
        cp_wait1();
        __syncthreads();
        if (it + 2 < Kt)
            g_load_stage<MASKED>(smb + ((it + 2) % 3) * GSTG, Ahi, Alo, Bhi, Blo,
                                 row0, col0, it + 2, K, nValid, tid);
        cp_commit();

        const uint32_t sb = smb + (it % 3) * GSTG;
#pragma unroll
        for (int k16 = 0; k16 < 2; k16++) {
            uint32_t aH[4][4], aL[4][4], bH[2][4], bL[2][4];
#pragma unroll
            for (int mt = 0; mt < 4; mt++) {
                uint32_t off = (uint32_t)((aRow + mt * 16) * 64
                             + (((k16 * 2 + aKch) ^ xorv) * 16));
                ldsm4(aH[mt], sb + off);
                ldsm4(aL[mt], sb + 8192 + off);
            }
#pragma unroll
            for (int nh = 0; nh < 2; nh++) {
                uint32_t off = (uint32_t)((bRow + nh * 16) * 64
                             + (((k16 * 2 + bKch) ^ xorv) * 16));
                ldsm4(bH[nh], sb + 16384 + off);
                ldsm4(bL[nh], sb + 24576 + off);
            }
#pragma unroll
            for (int mt = 0; mt < 4; mt++)
#pragma unroll
                for (int nt = 0; nt < 4; nt++)
                    mma16816(acc[mt][nt], aH[mt], &bH[nt >> 1][(nt & 1) * 2]);
#pragma unroll
            for (int mt = 0; mt < 4; mt++)
#pragma unroll
                for (int nt = 0; nt < 4; nt++)
                    mma16816(acc[mt][nt], aH[mt], &bL[nt >> 1][(nt & 1) * 2]);
#pragma unroll
            for (int mt = 0; mt < 4; mt++)
#pragma unroll
                for (int nt = 0; nt < 4; nt++)
                    mma16816(acc[mt][nt], aL[mt], &bH[nt >> 1][(nt & 1) * 2]);
        }
    }

    const int gid = lane >> 2, tg = lane & 3;
#pragma unroll
    for (int mt = 0; mt < 4; mt++) {
        const int r1 = row0 + warpM * 64 + mt * 16 + gid;
#pragma unroll
        for (int nt = 0; nt < 4; nt++) {
            const int c = col0 + warpN * 32 + nt * 8 + tg * 2;
            if (MASKED && c >= nValid) continue;
            const float b0 = bias[c], b1 = bias[c + 1];
            float v00 = acc[mt][nt][0] + b0, v01 = acc[mt][nt][1] + b1;
            float v10 = acc[mt][nt][2] + b0, v11 = acc[mt][nt][3] + b1;
            if (resHi) {
                __nv_bfloat162 rh0 = *(const __nv_bfloat162*)(resHi + (size_t)r1 * ldC + c);
                __nv_bfloat162 rl0 = *(const __nv_bfloat162*)(resLo + (size_t)r1 * ldC + c);
                __nv_bfloat162 rh1 = *(const __nv_bfloat162*)(resHi + (size_t)(r1 + 8) * ldC + c);
                __nv_bfloat162 rl1 = *(const __nv_bfloat162*)(resLo + (size_t)(r1 + 8) * ldC + c);
                v00 += __bfloat162float(rh0.x) + __bfloat162float(rl0.x);
                v01 += __bfloat162float(rh0.y) + __bfloat162float(rl0.y);
                v10 += __bfloat162float(rh1.x) + __bfloat162float(rl1.x);
                v11 += __bfloat162float(rh1.y) + __bfloat162float(rl1.y);
            }
            if (relu) {
                v00 = fmaxf(v00, 0.f); v01 = fmaxf(v01, 0.f);
                v10 = fmaxf(v10, 0.f); v11 = fmaxf(v11, 0.f);
            }
            if (Cf) {
                *(float2*)(Cf + (size_t)r1 * ldC + c)       = make_float2(v00, v01);
                *(float2*)(Cf + (size_t)(r1 + 8) * ldC + c) = make_float2(v10, v11);
            }
            if (Chi) {
                __nv_bfloat162 h, l;
                split2(v00, v01, &h, &l);
                *(__nv_bfloat162*)(Chi + (size_t)r1 * ldC + c) = h;
                *(__nv_bfloat162*)(Clo + (size_t)r1 * ldC + c) = l;
                split2(v10, v11, &h, &l);
                *(__nv_bfloat162*)(Chi + (size_t)(r1 + 8) * ldC + c) = h;
                *(__nv_bfloat162*)(Clo + (size_t)(r1 + 8) * ldC + c) = l;
            }
        }
    }
}

template <bool MASKED>
__global__ void __launch_bounds__(256, 2) gemm_mma_kernel(
    const __nv_bfloat16* __restrict__ Ahi, const __nv_bfloat16* __restrict__ Alo,
    const __nv_bfloat16* __restrict__ Bhi, const __nv_bfloat16* __restrict__ Blo,
    const float* __restrict__ bias,
    const __nv_bfloat16* __restrict__ resHi, const __nv_bfloat16* __restrict__ resLo,
    float* __restrict__ Cf,
    __nv_bfloat16* __restrict__ Chi, __nv_bfloat16* __restrict__ Clo,
    int K, int ldC, int nValid, int relu)
{
    extern __shared__ char gsm[];
    gemm_core<MASKED>(smem_u32(gsm), Ahi, Alo, Bhi, Blo, bias, resHi, resLo,
                      Cf, Chi, Clo, K, ldC, nValid, relu,
                      blockIdx.y * 128, blockIdx.x * 128);
}

// Merged QKV: grid (24, 32); blockIdx.x>>3 selects Q/K/V, &7 is the col tile.
__global__ void __launch_bounds__(256, 2) gemm_qkv_kernel(
    const __nv_bfloat16* __restrict__ Ahi, const __nv_bfloat16* __restrict__ Alo,
    const __nv_bfloat16* __restrict__ wH, const __nv_bfloat16* __restrict__ wL,
    int layer,
    const float* __restrict__ bq, const float* __restrict__ bk,
    const float* __restrict__ bv,
    __nv_bfloat16* __restrict__ qHi, __nv_bfloat16* __restrict__ qLo,
    __nv_bfloat16* __restrict__ kHi, __nv_bfloat16* __restrict__ kLo,
    __nv_bfloat16* __restrict__ vHi, __nv_bfloat16* __restrict__ vLo)
{
    extern __shared__ char gsm[];
    const int sel  = blockIdx.x >> 3;
    const int col0 = (blockIdx.x & 7) * 128;
    const size_t woff = (size_t)sel * WSZ + (size_t)layer * D_MODEL * D_MODEL;
    const float* bias = (sel == 0) ? (bq + layer * D_MODEL)
                      : (sel == 1) ? (bk + layer * D_MODEL)
                                   : (bv + layer * D_MODEL);
    __nv_bfloat16* Chi = (sel == 0) ? qHi : (sel == 1) ? kHi : vHi;
    __nv_bfloat16* Clo = (sel == 0) ? qLo : (sel == 1) ? kLo : vLo;
    gemm_core<false>(smem_u32(gsm), Ahi, Alo, wH + woff, wL + woff, bias,
                     nullptr, nullptr, nullptr, Chi, Clo,
                     D_MODEL, D_MODEL, D_MODEL, 0, blockIdx.y * 128, col0);
}

// ======================= mma.sync flash attention (bf16x3) ==================
// 512 blocks of 128 threads (4 warps), 64 q rows per block, single 64KB KV
// buffer -> 96KB smem -> 2 CTAs/SM. Q fragments hoisted into registers once.
// LPT order: qt = 15 - (bid>>5).
#define ATT_SMEM (32768 + 65536)

__device__ __forceinline__ void att_load_kv(
    uint32_t sb, const __nv_bfloat16* Khi, const __nv_bfloat16* Klo,
    const __nv_bfloat16* Vhi, const __nv_bfloat16* Vlo, int kvrow0, int hd, int tid)
{
#pragma unroll
    for (int i = 0; i < 16; i++) {
        int idx = tid + i * 128;
        int mat = idx >> 10, rem = idx & 1023;
        int r = rem >> 4, c = rem & 15;
        uint32_t so = (uint32_t)(mat * 16384 + (c >> 2) * 4096 + r * 64
                    + (((c & 3) ^ ((r >> 1) & 3)) * 16));
        cpasync16(sb + so, (mat ? Klo : Khi)
            + (size_t)(kvrow0 + r) * D_MODEL + hd * 128 + c * 8);
    }
#pragma unroll
    for (int i = 0; i < 16; i++) {
        int idx = tid + i * 128;
        int mat = idx >> 10, rem = idx & 1023;
        int r = rem >> 4, c = rem & 15;
        uint32_t so = (uint32_t)(32768 + mat * 16384 + r * 256
                    + (((c & 8) | ((c & 7) ^ (r & 7))) * 16));
        cpasync16(sb + so, (mat ? Vlo : Vhi)
            + (size_t)(kvrow0 + r) * D_MODEL + hd * 128 + c * 8);
    }
}

__global__ void __launch_bounds__(128) attn_mma_kernel(
    const __nv_bfloat16* __restrict__ Qhi, const __nv_bfloat16* __restrict__ Qlo,
    const __nv_bfloat16* __restrict__ Khi, const __nv_bfloat16* __restrict__ Klo,
    const __nv_bfloat16* __restrict__ Vhi, const __nv_bfloat16* __restrict__ Vlo,
    __nv_bfloat16* __restrict__ Ohi, __nv_bfloat16* __restrict__ Olo)
{
    extern __shared__ char smraw[];
    const uint32_t smbQ = smem_u32(smraw);
    const uint32_t sb   = smbQ + 32768;     // single KV buffer
    const int tid = threadIdx.x, lane = tid & 31, warp = tid >> 5;  // 0..3
    const int sub = lane & 7, tl = lane >> 3;
    const int xorv = (sub >> 1) & 3;
    const int qaRow = warp * 16 + (tl & 1) * 8 + sub;   // 0..63
    const int qaK = tl >> 1;
    const int kbRow = (tl >> 1) * 8 + sub;
    const int kbK = tl & 1;
    const int vRow = lane & 15, vC = (lane >> 4) & 1;

    // LPT: heaviest q-tiles first
    const int qt = 15 - ((int)blockIdx.x >> 5);
    const int bh = blockIdx.x & 31;
    const int bq = bh >> 3, hd = bh & 7;
    const int qrow0 = bq * N_PATCH + qt * 64;

    // load Q (64 x 128, hi/lo)
#pragma unroll
    for (int i = 0; i < 16; i++) {
        int idx = tid + i * 128;
        int mat = idx >> 10, rem = idx & 1023;
        int r = rem >> 4, c = rem & 15;
        uint32_t so = (uint32_t)(mat * 16384 + (c >> 2) * 4096 + r * 64
                    + (((c & 3) ^ ((r >> 1) & 3)) * 16));
        cpasync16(smbQ + so, (mat ? Qlo : Qhi)
            + (size_t)(qrow0 + r) * D_MODEL + hd * 128 + c * 8);
    }
    att_load_kv(sb, Khi, Klo, Vhi, Vlo, bq * N_PATCH, hd, tid);
    cp_commit();
    cp_wait0();
    __syncthreads();

    // hoist Q fragments into registers (loop-invariant)
    uint32_t qh[8][4], ql[8][4];
#pragma unroll
    for (int kk = 0; kk < 8; kk++) {
        uint32_t qoff = (uint32_t)((kk >> 1) * 4096 + qaRow * 64
                      + ((((kk & 1) * 2 + qaK) ^ xorv) * 16));
        ldsm4(qh[kk], smbQ + qoff);
        ldsm4(ql[kk], smbQ + 16384 + qoff);
    }

    float m0 = -1e30f, m1 = -1e30f, l0 = 0.f, l1 = 0.f;
    float O[16][4];
#pragma unroll
    for (int vt = 0; vt < 16; vt++)
#pragma unroll
        for (int e = 0; e < 4; e++) O[vt][e] = 0.f;

    const int nkv = qt + 1;
    for (int kt = 0; kt < nkv; kt++) {
        const int wrow = qt * 64 + warp * 16;
        {
            float s[8][4];
#pragma unroll
            for (int nt = 0; nt < 8; nt++)
#pragma unroll
                for (int e = 0; e < 4; e++) s[nt][e] = 0.f;

#pragma unroll
            for (int kk = 0; kk < 8; kk++) {
                uint32_t kh[4][4], kl[4][4];
#pragma unroll
                for (int n16 = 0; n16 < 4; n16++) {
                    uint32_t koff = (uint32_t)((kk >> 1) * 4096
                                  + (n16 * 16 + kbRow) * 64
                                  + ((((kk & 1) * 2 + kbK) ^ xorv) * 16));
                    ldsm4(kh[n16], sb + koff);
                    ldsm4(kl[n16], sb + 16384 + koff);
                }
#pragma unroll
                for (int n16 = 0; n16 < 4; n16++) {
                    mma16816(s[n16 * 2],     qh[kk], kh[n16]);
                    mma16816(s[n16 * 2 + 1], qh[kk], kh[n16] + 2);
                }
#pragma unroll
                for (int n16 = 0; n16 < 4; n16++) {
                    mma16816(s[n16 * 2],     qh[kk], kl[n16]);
                    mma16816(s[n16 * 2 + 1], qh[kk], kl[n16] + 2);
                }
#pragma unroll
                for (int n16 = 0; n16 < 4; n16++) {
                    mma16816(s[n16 * 2],     ql[kk], kh[n16]);
                    mma16816(s[n16 * 2 + 1], ql[kk], kh[n16] + 2);
                }
            }

            const int R0 = wrow + (lane >> 2), R1 = R0 + 8;
            const bool needMask = (kt * 64 + 63) > wrow;
#pragma unroll
            for (int nt = 0; nt < 8; nt++) {
                int C0 = kt * 64 + nt * 8 + (lane & 3) * 2;
                s[nt][0] *= ATTN_SCALE; s[nt][1] *= ATTN_SCALE;
                s[nt][2] *= ATTN_SCALE; s[nt][3] *= ATTN_SCALE;
                if (needMask) {
                    if (C0 > R0)     s[nt][0] = -1e30f;
                    if (C0 + 1 > R0) s[nt][1] = -1e30f;
                    if (C0 > R1)     s[nt][2] = -1e30f;
                    if (C0 + 1 > R1) s[nt][3] = -1e30f;
                }
            }

            float rm0 = -1e30f, rm1 = -1e30f;
#pragma unroll
            for (int nt = 0; nt < 8; nt++) {
                rm0 = fmaxf(rm0, fmaxf(s[nt][0], s[nt][1]));
                rm1 = fmaxf(rm1, fmaxf(s[nt][2], s[nt][3]));
            }
            rm0 = fmaxf(rm0, __shfl_xor_sync(0xffffffffu, rm0, 1));
            rm0 = fmaxf(rm0, __shfl_xor_sync(0xffffffffu, rm0, 2));
            rm1 = fmaxf(rm1, __shfl_xor_sync(0xffffffffu, rm1, 1));
            rm1 = fmaxf(rm1, __shfl_xor_sync(0xffffffffu, rm1, 2));

            float mn0 = fmaxf(m0, rm0), mn1 = fmaxf(m1, rm1);
            float a0 = __expf(m0 - mn0), a1 = __expf(m1 - mn1);
            m0 = mn0; m1 = mn1;

            float rs0 = 0.f, rs1 = 0.f;
#pragma unroll
            for (int nt = 0; nt < 8; nt++) {
                s[nt][0] = __expf(s[nt][0] - mn0);
                s[nt][1] = __expf(s[nt][1] - mn0);
                s[nt][2] = __expf(s[nt][2] - mn1);
                s[nt][3] = __expf(s[nt][3] - mn1);
                rs0 += s[nt][0] + s[nt][1];
                rs1 += s[nt][2] + s[nt][3];
            }
            rs0 += __shfl_xor_sync(0xffffffffu, rs0, 1);
            rs0 += __shfl_xor_sync(0xffffffffu, rs0, 2);
            rs1 += __shfl_xor_sync(0xffffffffu, rs1, 1);
            rs1 += __shfl_xor_sync(0xffffffffu, rs1, 2);
            l0 = l0 * a0 + rs0;
            l1 = l1 * a1 + rs1;

#pragma unroll
            for (int vt = 0; vt < 16; vt++) {
                O[vt][0] *= a0; O[vt][1] *= a0;
                O[vt][2] *= a1; O[vt][3] *= a1;
            }

#pragma unroll
            for (int kv16 = 0; kv16 < 4; kv16++) {
                uint32_t pH[4], pL[4];
                split2u(s[kv16*2][0],   s[kv16*2][1],   &pH[0], &pL[0]);
                split2u(s[kv16*2][2],   s[kv16*2][3],   &pH[1], &pL[1]);
                split2u(s[kv16*2+1][0], s[kv16*2+1][1], &pH[2], &pL[2]);
                split2u(s[kv16*2+1][2], s[kv16*2+1][3], &pH[3], &pL[3]);
#pragma unroll
                for (int vb = 0; vb < 2; vb++) {
                    uint32_t vh[4][4], vl[4][4];
#pragma unroll
                    for (int j = 0; j < 4; j++) {
                        int c = (vb * 4 + j) * 2 + vC;
                        int row = kv16 * 16 + vRow;
                        uint32_t swc = (uint32_t)((c & 8) | ((c & 7) ^ (row & 7)));
                        uint32_t voff = (uint32_t)(row * 256 + swc * 16);
                        ldsm4t(vh[j], sb + 32768 + voff);
                        ldsm4t(vl[j], sb + 49152 + voff);
                    }
#pragma unroll
                    for (int j = 0; j < 4; j++) {
                        int vn = vb * 4 + j;
                        mma16816(O[vn * 2],     pH, vh[j]);
                        mma16816(O[vn * 2 + 1], pH, vh[j] + 2);
                    }
#pragma unroll
                    for (int j = 0; j < 4; j++) {
                        int vn = vb * 4 + j;
                        mma16816(O[vn * 2],     pH, vl[j]);
                        mma16816(O[vn * 2 + 1], pH, vl[j] + 2);
                    }
#pragma unroll
                    for (int j = 0; j < 4; j++) {
                        int vn = vb * 4 + j;
                        mma16816(O[vn * 2],     pL, vh[j]);
                        mma16816(O[vn * 2 + 1], pL, vh[j] + 2);
                    }
                }
            }
        }

        if (kt + 1 < nkv) {
            __syncthreads();   // everyone done reading KV before overwrite
            att_load_kv(sb, Khi, Klo, Vhi, Vlo,
                        bq * N_PATCH + (kt + 1) * 64, hd, tid);
            cp_commit();
            cp_wait0();
            __syncthreads();
        }
    }

    const float inv0 = 1.f / l0, inv1 = 1.f / l1;
    const size_t r0 = (size_t)(qrow0 + warp * 16 + (lane >> 2)) * D_MODEL + hd * 128;
    const size_t r1 = r0 + 8 * D_MODEL;
#pragma unroll
    for (int vt = 0; vt < 16; vt++) {
        int c = vt * 8 + (lane & 3) * 2;
        __nv_bfloat162 h2, l2;
        split2(O[vt][0] * inv0, O[vt][1] * inv0, &h2, &l2);
        *(__nv_bfloat162*)(Ohi + r0 + c) = h2;
        *(__nv_bfloat162*)(Olo + r0 + c) = l2;
        split2(O[vt][2] * inv1, O[vt][3] * inv1, &h2, &l2);
        *(__nv_bfloat162*)(Ohi + r1 + c) = h2;
        *(__nv_bfloat162*)(Olo + r1 + c) = l2;
    }
}

// ======================= fp32 SGEMM (patch embedding) =======================
__global__ void __launch_bounds__(256) sgemm_kernel(
    const float* __restrict__ A, const float* __restrict__ W,
    __nv_bfloat16* __restrict__ Chi, __nv_bfloat16* __restrict__ Clo,
    int M, int N, int K)
{
    __shared__ float As[8 * 132];
    __shared__ float Bs[8 * 132];
    const int tid = threadIdx.x, tm = tid >> 4, tn = tid & 15;
    const int row0 = blockIdx.y * 128, col0 = blockIdx.x * 128;
    const int lrow = tid >> 1, lk = (tid & 1) * 4;
    const float* Ap = A + (size_t)(row0 + lrow) * K + lk;
    const float* Wp = W + (size_t)(col0 + lrow) * K + lk;

    float acc[8][8];
#pragma unroll
    for (int i = 0; i < 8; i++)
#pragma unroll
        for (int j = 0; j < 8; j++) acc[i][j] = 0.f;

    for (int kt = 0; kt < K; kt += 8) {
        float4 a4 = *(const float4*)(Ap + kt);
        float4 b4 = *(const float4*)(Wp + kt);
        __syncthreads();
        As[(lk+0)*132+lrow]=a4.x; As[(lk+1)*132+lrow]=a4.y;
        As[(lk+2)*132+lrow]=a4.z; As[(lk+3)*132+lrow]=a4.w;
        Bs[(lk+0)*132+lrow]=b4.x; Bs[(lk+1)*132+lrow]=b4.y;
        Bs[(lk+2)*132+lrow]=b4.z; Bs[(lk+3)*132+lrow]=b4.w;
        __syncthreads();
#pragma unroll
        for (int kk = 0; kk < 8; kk++) {
            float4 a0 = *(const float4*)&As[kk*132 + tm*4];
            float4 a1 = *(const float4*)&As[kk*132 + 64 + tm*4];
            float4 b0 = *(const float4*)&Bs[kk*132 + tn*4];
            float4 b1 = *(const float4*)&Bs[kk*132 + 64 + tn*4];
            float ar[8] = {a0.x,a0.y,a0.z,a0.w,a1.x,a1.y,a1.z,a1.w};
            float br[8] = {b0.x,b0.y,b0.z,b0.w,b1.x,b1.y,b1.z,b1.w};
#pragma unroll
            for (int i = 0; i < 8; i++)
#pragma unroll
                for (int j = 0; j < 8; j++)
                    acc[i][j] = fmaf(ar[i], br[j], acc[i][j]);
        }
    }

    float dv[8];
#pragma unroll
    for (int j = 0; j < 8; j++) {
        int c = col0 + ((j < 4) ? tn*4 + j : 64 + tn*4 + (j - 4));
        dv[j] = expf((float)(c & ~1) * PE_COEF);
    }
#pragma unroll
    for (int i = 0; i < 8; i++) {
        int r = row0 + ((i < 4) ? tm*4 + i : 64 + tm*4 + (i - 4));
        float pn = (float)(r & (N_PATCH - 1));
#pragma unroll
        for (int jb = 0; jb < 2; jb++) {
            int cb = col0 + (jb ? 64 + tn*4 : tn*4);
            float v[4];
#pragma unroll
            for (int qq = 0; qq < 4; qq++) {
                int j = jb*4 + qq;
                float ang = pn * dv[j];
                v[qq] = acc[i][j] + (((cb + qq) & 1) ? cosf(ang) : sinf(ang));
            }
            __nv_bfloat162 h, l;
            split2(v[0], v[1], &h, &l);
            *(__nv_bfloat162*)(Chi + (size_t)r * N + cb) = h;
            *(__nv_bfloat162*)(Clo + (size_t)r * N + cb) = l;
            split2(v[2], v[3], &h, &l);
            *(__nv_bfloat162*)(Chi + (size_t)r * N + cb + 2) = h;
            *(__nv_bfloat162*)(Clo + (size_t)r * N + cb + 2) = l;
        }
    }
}

// ======================= LayerNorm (fp32 in, bf16 pair out, opt fp32 out) ===
__global__ void __launch_bounds__(256) addln_kernel(
    const float* __restrict__ a,
    const float* __restrict__ g, const float* __restrict__ be,
    float* __restrict__ out,
    __nv_bfloat16* __restrict__ outHi, __nv_bfloat16* __restrict__ outLo)
{
    const int warp = threadIdx.x >> 5, lane = threadIdx.x & 31;
    const int row = blockIdx.x * 8 + warp;
    const float* ap = a + (size_t)row * D_MODEL;

    float x[32], sum = 0.f;
#pragma unroll
    for (int j = 0; j < 8; j++) {
        int col = j * 128 + lane * 4;
        float4 xv = *(const float4*)(ap + col);
        x[j*4+0]=xv.x; x[j*4+1]=xv.y; x[j*4+2]=xv.z; x[j*4+3]=xv.w;
        sum += xv.x + xv.y + xv.z + xv.w;
    }
#pragma unroll
    for (int o = 16; o > 0; o >>= 1) sum += __shfl_xor_sync(0xffffffffu, sum, o);
    const float mean = sum * (1.f / 1024.f);
    float vs = 0.f;
#pragma unroll
    for (int i = 0; i < 32; i++) { float d = x[i] - mean; vs = fmaf(d, d, vs); }
#pragma unroll
    for (int o = 16; o > 0; o >>= 1) vs += __shfl_xor_sync(0xffffffffu, vs, o);
    const float rstd = rsqrtf(vs * (1.f / 1024.f) + 1e-5f);

#pragma unroll
    for (int j = 0; j < 8; j++) {
        int col = j * 128 + lane * 4;
        float4 gv  = *(const float4*)(g + col);
        float4 bev = *(const float4*)(be + col);
        float4 ov;
        ov.x = (x[j*4+0]-mean)*rstd*gv.x + bev.x;
        ov.y = (x[j*4+1]-mean)*rstd*gv.y + bev.y;
        ov.z = (x[j*4+2]-mean)*rstd*gv.z + bev.z;
        ov.w = (x[j*4+3]-mean)*rstd*gv.w + bev.w;
        if (out) *(float4*)(out + (size_t)row * D_MODEL + col) = ov;
        __nv_bfloat162 h, l;
        split2(ov.x, ov.y, &h, &l);
        *(__nv_bfloat162*)(outHi + (size_t)row * D_MODEL + col) = h;
        *(__nv_bfloat162*)(outLo + (size_t)row * D_MODEL + col) = l;
        split2(ov.z, ov.w, &h, &l);
        *(__nv_bfloat162*)(outHi + (size_t)row * D_MODEL + col + 2) = h;
        *(__nv_bfloat162*)(outLo + (size_t)row * D_MODEL + col + 2) = l;
    }
}

#define GETSYM(var, sym) cudaGetSymbolAddress((void**)&var, sym)

extern "C" void kernel_launch(void* const* d_in, const int* in_sizes, int n_in,
                              void* d_out, int out_size)
{
    const float* x     = (const float*)d_in[0];
    const float* W_emb = (const float*)d_in[1];
    const float* Wq    = (const float*)d_in[2];
    const float* bq    = (const float*)d_in[3];
    const float* Wk    = (const float*)d_in[4];
    const float* bk    = (const float*)d_in[5];
    const float* Wv    = (const float*)d_in[6];
    const float* bv    = (const float*)d_in[7];
    const float* Wo    = (const float*)d_in[8];
    const float* bo    = (const float*)d_in[9];
    const float* Wc1   = (const float*)d_in[10];
    const float* bc1   = (const float*)d_in[11];
    const float* Wc2   = (const float*)d_in[12];
    const float* bc2   = (const float*)d_in[13];
    const float* g1    = (const float*)d_in[14];
    const float* be1   = (const float*)d_in[15];
    const float* g2    = (const float*)d_in[16];
    const float* be2   = (const float*)d_in[17];
    const float* gN    = (const float*)d_in[18];
    const float* beN   = (const float*)d_in[19];
    const float* Wp    = (const float*)d_in[20];
    const float* bp    = (const float*)d_in[21];

    float *h, *tmp;
    GETSYM(h, g_h); GETSYM(tmp, g_tmp);

    __nv_bfloat16 *hHi, *hLo, *qHi, *qLo, *kHi, *kLo, *vHi, *vLo,
                  *attHi, *attLo, *ffHi, *ffLo,
                  *wqkvH, *wqkvL, *woH, *woL, *w1H, *w1L, *w2H, *w2L, *wpH, *wpL;
    GETSYM(hHi, g_h_hi); GETSYM(hLo, g_h_lo);
    GETSYM(qHi, g_q_hi); GETSYM(qLo, g_q_lo);
    GETSYM(kHi, g_k_hi); GETSYM(kLo, g_k_lo);
    GETSYM(vHi, g_v_hi); GETSYM(vLo, g_v_lo);
    GETSYM(attHi, g_att_hi); GETSYM(attLo, g_att_lo);
    GETSYM(ffHi, g_ff_hi); GETSYM(ffLo, g_ff_lo);
    GETSYM(wqkvH, g_wqkv_hi); GETSYM(wqkvL, g_wqkv_lo);
    GETSYM(woH, g_wo_hi); GETSYM(woL, g_wo_lo);
    GETSYM(w1H, g_w1_hi); GETSYM(w1L, g_w1_lo);
    GETSYM(w2H, g_w2_hi); GETSYM(w2L, g_w2_lo);
    GETSYM(wpH, g_wp_hi); GETSYM(wpL, g_wp_lo);

    cudaFuncSetAttribute(attn_mma_kernel, cudaFuncAttributeMaxDynamicSharedMemorySize, ATT_SMEM);
    cudaFuncSetAttribute(gemm_mma_kernel<false>, cudaFuncAttributeMaxDynamicSharedMemorySize, GSMEM);
    cudaFuncSetAttribute(gemm_mma_kernel<true>, cudaFuncAttributeMaxDynamicSharedMemorySize, GSMEM);
    cudaFuncSetAttribute(gemm_qkv_kernel, cudaFuncAttributeMaxDynamicSharedMemorySize, GSMEM);

    dim3 blk(256);
    const dim3 gQKV (24, M_ROWS / 128);
    const dim3 gONE (D_MODEL / 128, M_ROWS / 128);
    const dim3 gFF1 (D_FF   / 128, M_ROWS / 128);
    const dim3 gPROJ(1, M_ROWS / 128);

    cvt3_kernel<<<dim3(WSZ / 4 / 256, 3), blk>>>(Wq, Wk, Wv, wqkvH, wqkvL);
    sgemm_kernel<<<dim3(8, 32), blk>>>(x, W_emb, hHi, hLo, M_ROWS, D_MODEL, P_LEN);
    cvt_pair_kernel<<<P_LEN * D_MODEL / 4 / 256, blk>>>(Wp, wpH, wpL, P_LEN * D_MODEL / 4);

    bool first = true;
    for (int i = 0; i < E_LAYERS; i++) {
        const size_t wo_ = (size_t)i * D_MODEL * D_MODEL;
        const size_t wf_ = (size_t)i * D_FF * D_MODEL;

        gemm_qkv_kernel<<<gQKV, blk, GSMEM>>>(hHi, hLo, wqkvH, wqkvL, i,
            bq, bk, bv, qHi, qLo, kHi, kLo, vHi, vLo);

        if (first) {
            cvt_pair_kernel<<<WSZ / 4 / 256, blk>>>(Wo,  woH, woL, WSZ / 4);
            cvt_pair_kernel<<<WFF / 4 / 256, blk>>>(Wc1, w1H, w1L, WFF / 4);
            cvt_pair_kernel<<<WFF / 4 / 256, blk>>>(Wc2, w2H, w2L, WFF / 4);
            first = false;
        }

        attn_mma_kernel<<<512, 128, ATT_SMEM>>>(qHi, qLo, kHi, kLo, vHi, vLo,
                                                attHi, attLo);

        // tmp = (hHi+hLo) + att @ Wo^T + bo
        gemm_mma_kernel<false><<<gONE, blk, GSMEM>>>(attHi, attLo, woH + wo_,
            woL + wo_, bo + i * D_MODEL, hHi, hLo, tmp, nullptr, nullptr,
            D_MODEL, D_MODEL, D_MODEL, 0);
        addln_kernel<<<512, blk>>>(tmp, g1 + i * D_MODEL, be1 + i * D_MODEL,
                                   nullptr, hHi, hLo);

        gemm_mma_kernel<false><<<gFF1, blk, GSMEM>>>(hHi, hLo, w1H + wf_,
            w1L + wf_, bc1 + i * D_FF, nullptr, nullptr, nullptr, ffHi, ffLo,
            D_MODEL, D_FF, D_FF, 1);
        gemm_mma_kernel<false><<<gONE, blk, GSMEM>>>(ffHi, ffLo, w2H + wf_,
            w2L + wf_, bc2 + i * D_MODEL, hHi, hLo, tmp, nullptr, nullptr,
            D_FF, D_MODEL, D_MODEL, 0);
        addln_kernel<<<512, blk>>>(tmp, g2 + i * D_MODEL, be2 + i * D_MODEL,
                                   (i == E_LAYERS - 1) ? h : nullptr, hHi, hLo);
    }

    addln_kernel<<<512, blk>>>(h, gN, beN, nullptr, qHi, qLo);
    gemm_mma_kernel<true><<<gPROJ, blk, GSMEM>>>(qHi, qLo, wpH, wpL, bp,
        nullptr, nullptr, (float*)d_out, nullptr, nullptr,
        D_MODEL, P_LEN, P_LEN, 0);
}

// round 16
// speedup vs baseline: 1.0100x; 1.0100x over previous
#include <cuda_runtime.h>
#include <cuda_bf16.h>
#include <math.h>
#include <stdint.h>

#define D_MODEL 1024
#define N_PATCH 1024
#define M_ROWS 4096
#define D_FF 2048
#define E_LAYERS 8
#define P_LEN 96
#define PE_COEF (-0.0089944730195079915f)
#define ATTN_SCALE 0.08838834764831845f
#define WSZ (E_LAYERS * D_MODEL * D_MODEL)
#define WFF (E_LAYERS * D_FF * D_MODEL)

__device__ float g_h  [M_ROWS * D_MODEL];
__device__ float g_tmp[M_ROWS * D_MODEL];
__device__ __nv_bfloat16 g_h_hi[M_ROWS*D_MODEL], g_h_lo[M_ROWS*D_MODEL];
__device__ __nv_bfloat16 g_q_hi[M_ROWS*D_MODEL], g_q_lo[M_ROWS*D_MODEL];
__device__ __nv_bfloat16 g_k_hi[M_ROWS*D_MODEL], g_k_lo[M_ROWS*D_MODEL];
__device__ __nv_bfloat16 g_v_hi[M_ROWS*D_MODEL], g_v_lo[M_ROWS*D_MODEL];
__device__ __nv_bfloat16 g_att_hi[M_ROWS*D_MODEL], g_att_lo[M_ROWS*D_MODEL];
__device__ __nv_bfloat16 g_ff_hi[M_ROWS*D_FF], g_ff_lo[M_ROWS*D_FF];
__device__ __nv_bfloat16 g_wqkv_hi[3 * WSZ], g_wqkv_lo[3 * WSZ];
__device__ __nv_bfloat16 g_wo_hi[WSZ], g_wo_lo[WSZ];
__device__ __nv_bfloat16 g_w1_hi[WFF], g_w1_lo[WFF];
__device__ __nv_bfloat16 g_w2_hi[WFF], g_w2_lo[WFF];
__device__ __nv_bfloat16 g_wp_hi[P_LEN*D_MODEL], g_wp_lo[P_LEN*D_MODEL];

__device__ __forceinline__ uint32_t smem_u32(const void* p) {
    uint32_t a;
    asm("{ .reg .u64 t; cvta.to.shared.u64 t, %1; cvt.u32.u64 %0, t; }" : "=r"(a) : "l"(p));
    return a;
}
__device__ __forceinline__ void cpasync16(uint32_t d, const void* s) {
    asm volatile("cp.async.cg.shared.global [%0], [%1], 16;" :: "r"(d), "l"(s) : "memory");
}
__device__ __forceinline__ void cpasync16z(uint32_t d, const void* s, int sz) {
    asm volatile("cp.async.cg.shared.global [%0], [%1], 16, %2;" :: "r"(d), "l"(s), "r"(sz) : "memory");
}
__device__ __forceinline__ void cp_commit(){ asm volatile("cp.async.commit_group;":::"memory"); }
__device__ __forceinline__ void cp_wait1(){ asm volatile("cp.async.wait_group 1;":::"memory"); }
__device__ __forceinline__ void cp_wait0(){ asm volatile("cp.async.wait_group 0;":::"memory"); }
__device__ __forceinline__ void ldsm4(uint32_t* r, uint32_t a) {
    asm volatile("ldmatrix.sync.aligned.m8n8.x4.shared.b16 {%0,%1,%2,%3}, [%4];"
                 : "=r"(r[0]), "=r"(r[1]), "=r"(r[2]), "=r"(r[3]) : "r"(a));
}
__device__ __forceinline__ void ldsm4t(uint32_t* r, uint32_t a) {
    asm volatile("ldmatrix.sync.aligned.m8n8.x4.trans.shared.b16 {%0,%1,%2,%3}, [%4];"
                 : "=r"(r[0]), "=r"(r[1]), "=r"(r[2]), "=r"(r[3]) : "r"(a));
}
__device__ __forceinline__ void mma16816(float* d, const uint32_t* a, const uint32_t* b) {
    asm volatile("mma.sync.aligned.m16n8k16.row.col.f32.bf16.bf16.f32 "
        "{%0,%1,%2,%3}, {%4,%5,%6,%7}, {%8,%9}, {%0,%1,%2,%3};"
        : "+f"(d[0]), "+f"(d[1]), "+f"(d[2]), "+f"(d[3])
        : "r"(a[0]), "r"(a[1]), "r"(a[2]), "r"(a[3]), "r"(b[0]), "r"(b[1]));
}
__device__ __forceinline__ void split2(float v0, float v1, __nv_bfloat162* hi, __nv_bfloat162* lo) {
    __nv_bfloat16 h0 = __float2bfloat16_rn(v0), h1 = __float2bfloat16_rn(v1);
    lo->x = __float2bfloat16_rn(v0 - __bfloat162float(h0));
    lo->y = __float2bfloat16_rn(v1 - __bfloat162float(h1));
    hi->x = h0; hi->y = h1;
}
__device__ __forceinline__ void split2u(float v0, float v1, uint32_t* hi, uint32_t* lo) {
    __nv_bfloat162 h, l;
    split2(v0, v1, &h, &l);
    *hi = *reinterpret_cast<uint32_t*>(&h);
    *lo = *reinterpret_cast<uint32_t*>(&l);
}

// ======================= weight converters ==================================
__global__ void __launch_bounds__(256) cvt_pair_kernel(
    const float* __restrict__ w, __nv_bfloat16* __restrict__ hi,
    __nv_bfloat16* __restrict__ lo, int n4)
{
    int i = blockIdx.x * 256 + threadIdx.x;
    if (i >= n4) return;
    float4 x = ((const float4*)w)[i];
    __nv_bfloat162 h0, l0, h1, l1;
    split2(x.x, x.y, &h0, &l0);
    split2(x.z, x.w, &h1, &l1);
    ((__nv_bfloat162*)hi)[i*2+0] = h0; ((__nv_bfloat162*)hi)[i*2+1] = h1;
    ((__nv_bfloat162*)lo)[i*2+0] = l0; ((__nv_bfloat162*)lo)[i*2+1] = l1;
}

__global__ void __launch_bounds__(256) cvt3_kernel(
    const float* __restrict__ w0, const float* __restrict__ w1,
    const float* __restrict__ w2,
    __nv_bfloat16* __restrict__ hi, __nv_bfloat16* __restrict__ lo)
{
    const int sel = blockIdx.y;
    const float* w = (sel == 0) ? w0 : (sel == 1) ? w1 : w2;
    int i = blockIdx.x * 256 + threadIdx.x;
    float4 x = ((const float4*)w)[i];
    size_t base = (size_t)sel * (WSZ / 2);
    __nv_bfloat162 h0, l0, h1, l1;
    split2(x.x, x.y, &h0, &l0);
    split2(x.z, x.w, &h1, &l1);
    ((__nv_bfloat162*)hi)[base + i*2+0] = h0;
    ((__nv_bfloat162*)hi)[base + i*2+1] = h1;
    ((__nv_bfloat162*)lo)[base + i*2+0] = l0;
    ((__nv_bfloat162*)lo)[base + i*2+1] = l1;
}

// ======================= bf16x3 GEMM core ====================================
#define GSTG 32768
#define GSMEM (3 * GSTG)

template <bool MASKED>
__device__ __forceinline__ void g_load_stage(
    uint32_t sb, const __nv_bfloat16* Ahi, const __nv_bfloat16* Alo,
    const __nv_bfloat16* Bhi, const __nv_bfloat16* Blo,
    int row0, int col0, int kt, int K, int nValid, int tid)
{
#pragma unroll
    for (int i = 0; i < 2; i++) {
        int idx = tid + i * 256;
        int r = idx >> 2, c = idx & 3;
        uint32_t so = (uint32_t)(r * 64 + ((c ^ ((r >> 1) & 3)) * 16));
        size_t aoff = (size_t)(row0 + r) * K + kt * 32 + c * 8;
        cpasync16(sb + so,        Ahi + aoff);
        cpasync16(sb + 8192 + so, Alo + aoff);
        if (MASKED) {
            int br = col0 + r;
            int sz = (br < nValid) ? 16 : 0;
            if (br >= nValid) br = nValid - 1;
            size_t boff = (size_t)br * K + kt * 32 + c * 8;
            cpasync16z(sb + 16384 + so, Bhi + boff, sz);
            cpasync16z(sb + 24576 + so, Blo + boff, sz);
        } else {
            size_t boff = (size_t)(col0 + r) * K + kt * 32 + c * 8;
            cpasync16(sb + 16384 + so, Bhi + boff);
            cpasync16(sb + 24576 + so, Blo + boff);
        }
    }
}

template <bool MASKED>
__device__ __forceinline__ void gemm_core(
    uint32_t smb, const __nv_bfloat16* Ahi, const __nv_bfloat16* Alo,
    const __nv_bfloat16* Bhi, const __nv_bfloat16* Blo,
    const float* bias,
    const __nv_bfloat16* resHi, const __nv_bfloat16* resLo,
    float* Cf, __nv_bfloat16* Chi, __nv_bfloat16* Clo,
    int K, int ldC, int nValid, int relu, int row0, int col0)
{
    const int tid = threadIdx.x, lane = tid & 31, warp = tid >> 5;
    const int warpM = warp >> 2, warpN = warp & 3;
    const int sub = lane & 7, tile = lane >> 3;
    const int xorv = (sub >> 1) & 3;
    const int aRow = warpM * 64 + (tile & 1) * 8 + sub;
    const int aKch = tile >> 1;
    const int bRow = warpN * 32 + (tile >> 1) * 8 + sub;
    const int bKch = tile & 1;

    float acc[4][4][4];
#pragma unroll
    for (int mt = 0; mt < 4; mt++)
#pragma unroll
        for (int nt = 0; nt < 4; nt++)
#pragma unroll
            for (int e = 0; e < 4; e++) acc[mt][nt][e] = 0.f;

    const int Kt = K >> 5;
    g_load_stage<MASKED>(smb, Ahi, Alo, Bhi, Blo, row0, col0, 0, K, nValid, tid);
    cp_commit();
    g_load_stage<MASKED>(smb + GSTG, Ahi, Alo, Bhi, Blo, row0, col0, 1, K, nValid, tid);
    cp_commit();

    for (int it = 0; it < Kt; it++) {
        cp_wait1();
        __syncthreads();
        if (it + 2 < Kt)
            g_load_stage<MASKED>(smb + ((it + 2) % 3) * GSTG, Ahi, Alo, Bhi, Blo,
                                 row0, col0, it + 2, K, nValid, tid);
        cp_commit();

        const uint32_t sb = smb + (it % 3) * GSTG;
#pragma unroll
        for (int k16 = 0; k16 < 2; k16++) {
            uint32_t aH[4][4], aL[4][4], bH[2][4], bL[2][4];
#pragma unroll
            for (int mt = 0; mt < 4; mt++) {
                uint32_t off = (uint32_t)((aRow + mt * 16) * 64
                             + (((k16 * 2 + aKch) ^ xorv) * 16));
                ldsm4(aH[mt], sb + off);
                ldsm4(aL[mt], sb + 8192 + off);
            }
#pragma unroll
            for (int nh = 0; nh < 2; nh++) {
                uint32_t off = (uint32_t)((bRow + nh * 16) * 64
                             + (((k16 * 2 + bKch) ^ xorv) * 16));
                ldsm4(bH[nh], sb + 16384 + off);
                ldsm4(bL[nh], sb + 24576 + off);
            }
#pragma unroll
            for (int mt = 0; mt < 4; mt++)
#pragma unroll
                for (int nt = 0; nt < 4; nt++)
                    mma16816(acc[mt][nt], aH[mt], &bH[nt >> 1][(nt & 1) * 2]);
#pragma unroll
            for (int mt = 0; mt < 4; mt++)
#pragma unroll
                for (int nt = 0; nt < 4; nt++)
                    mma16816(acc[mt][nt], aH[mt], &bL[nt >> 1][(nt & 1) * 2]);
#pragma unroll
            for (int mt = 0; mt < 4; mt++)
#pragma unroll
                for (int nt = 0; nt < 4; nt++)
                    mma16816(acc[mt][nt], aL[mt], &bH[nt >> 1][(nt & 1) * 2]);
        }
    }

    const int gid = lane >> 2, tg = lane & 3;
#pragma unroll
    for (int mt = 0; mt < 4; mt++) {
        const int r1 = row0 + warpM * 64 + mt * 16 + gid;
#pragma unroll
        for (int nt = 0; nt < 4; nt++) {
            const int c = col0 + warpN * 32 + nt * 8 + tg * 2;
            if (MASKED && c >= nValid) continue;
            const float b0 = bias[c], b1 = bias[c + 1];
            float v00 = acc[mt][nt][0] + b0, v01 = acc[mt][nt][1] + b1;
            float v10 = acc[mt][nt][2] + b0, v11 = acc[mt][nt][3] + b1;
            if (resHi) {
                __nv_bfloat162 rh0 = *(const __nv_bfloat162*)(resHi + (size_t)r1 * ldC + c);
                __nv_bfloat162 rl0 = *(const __nv_bfloat162*)(resLo + (size_t)r1 * ldC + c);
                __nv_bfloat162 rh1 = *(const __nv_bfloat162*)(resHi + (size_t)(r1 + 8) * ldC + c);
                __nv_bfloat162 rl1 = *(const __nv_bfloat162*)(resLo + (size_t)(r1 + 8) * ldC + c);
                v00 += __bfloat162float(rh0.x) + __bfloat162float(rl0.x);
                v01 += __bfloat162float(rh0.y) + __bfloat162float(rl0.y);
                v10 += __bfloat162float(rh1.x) + __bfloat162float(rl1.x);
                v11 += __bfloat162float(rh1.y) + __bfloat162float(rl1.y);
            }
            if (relu) {
                v00 = fmaxf(v00, 0.f); v01 = fmaxf(v01, 0.f);
                v10 = fmaxf(v10, 0.f); v11 = fmaxf(v11, 0.f);
            }
            if (Cf) {
                *(float2*)(Cf + (size_t)r1 * ldC + c)       = make_float2(v00, v01);
                *(float2*)(Cf + (size_t)(r1 + 8) * ldC + c) = make_float2(v10, v11);
            }
            if (Chi) {
                __nv_bfloat162 h, l;
                split2(v00, v01, &h, &l);
                *(__nv_bfloat162*)(Chi + (size_t)r1 * ldC + c) = h;
                *(__nv_bfloat162*)(Clo + (size_t)r1 * ldC + c) = l;
                split2(v10, v11, &h, &l);
                *(__nv_bfloat162*)(Chi + (size_t)(r1 + 8) * ldC + c) = h;
                *(__nv_bfloat162*)(Clo + (size_t)(r1 + 8) * ldC + c) = l;
            }
        }
    }
}

template <bool MASKED>
__global__ void __launch_bounds__(256, 2) gemm_mma_kernel(
    const __nv_bfloat16* __restrict__ Ahi, const __nv_bfloat16* __restrict__ Alo,
    const __nv_bfloat16* __restrict__ Bhi, const __nv_bfloat16* __restrict__ Blo,
    const float* __restrict__ bias,
    const __nv_bfloat16* __restrict__ resHi, const __nv_bfloat16* __restrict__ resLo,
    float* __restrict__ Cf,
    __nv_bfloat16* __restrict__ Chi, __nv_bfloat16* __restrict__ Clo,
    int K, int ldC, int nValid, int relu)
{
    extern __shared__ char gsm[];
    gemm_core<MASKED>(smem_u32(gsm), Ahi, Alo, Bhi, Blo, bias, resHi, resLo,
                      Cf, Chi, Clo, K, ldC, nValid, relu,
                      blockIdx.y * 128, blockIdx.x * 128);
}

// Merged QKV: grid (24, 32); blockIdx.x>>3 selects Q/K/V, &7 is the col tile.
__global__ void __launch_bounds__(256, 2) gemm_qkv_kernel(
    const __nv_bfloat16* __restrict__ Ahi, const __nv_bfloat16* __restrict__ Alo,
    const __nv_bfloat16* __restrict__ wH, const __nv_bfloat16* __restrict__ wL,
    int layer,
    const float* __restrict__ bq, const float* __restrict__ bk,
    const float* __restrict__ bv,
    __nv_bfloat16* __restrict__ qHi, __nv_bfloat16* __restrict__ qLo,
    __nv_bfloat16* __restrict__ kHi, __nv_bfloat16* __restrict__ kLo,
    __nv_bfloat16* __restrict__ vHi, __nv_bfloat16* __restrict__ vLo)
{
    extern __shared__ char gsm[];
    const int sel  = blockIdx.x >> 3;
    const int col0 = (blockIdx.x & 7) * 128;
    const size_t woff = (size_t)sel * WSZ + (size_t)layer * D_MODEL * D_MODEL;
    const float* bias = (sel == 0) ? (bq + layer * D_MODEL)
                      : (sel == 1) ? (bk + layer * D_MODEL)
                                   : (bv + layer * D_MODEL);
    __nv_bfloat16* Chi = (sel == 0) ? qHi : (sel == 1) ? kHi : vHi;
    __nv_bfloat16* Clo = (sel == 0) ? qLo : (sel == 1) ? kLo : vLo;
    gemm_core<false>(smem_u32(gsm), Ahi, Alo, wH + woff, wL + woff, bias,
                     nullptr, nullptr, nullptr, Chi, Clo,
                     D_MODEL, D_MODEL, D_MODEL, 0, blockIdx.y * 128, col0);
}

// ======================= mma.sync flash attention (bf16x3) ==================
// 512 blocks of 128 threads (4 warps), 64 q rows per block, single 64KB KV
// buffer -> 96KB smem -> 2 CTAs/SM. LPT order: qt = 15 - (bid>>5).
#define ATT_SMEM (32768 + 65536)

__device__ __forceinline__ void att_load_kv(
    uint32_t sb, const __nv_bfloat16* Khi, const __nv_bfloat16* Klo,
    const __nv_bfloat16* Vhi, const __nv_bfloat16* Vlo, int kvrow0, int hd, int tid)
{
#pragma unroll
    for (int i = 0; i < 16; i++) {
        int idx = tid + i * 128;
        int mat = idx >> 10, rem = idx & 1023;
        int r = rem >> 4, c = rem & 15;
        uint32_t so = (uint32_t)(mat * 16384 + (c >> 2) * 4096 + r * 64
                    + (((c & 3) ^ ((r >> 1) & 3)) * 16));
        cpasync16(sb + so, (mat ? Klo : Khi)
            + (size_t)(kvrow0 + r) * D_MODEL + hd * 128 + c * 8);
    }
#pragma unroll
    for (int i = 0; i < 16; i++) {
        int idx = tid + i * 128;
        int mat = idx >> 10, rem = idx & 1023;
        int r = rem >> 4, c = rem & 15;
        uint32_t so = (uint32_t)(32768 + mat * 16384 + r * 256
                    + (((c & 8) | ((c & 7) ^ (r & 7))) * 16));
        cpasync16(sb + so, (mat ? Vlo : Vhi)
            + (size_t)(kvrow0 + r) * D_MODEL + hd * 128 + c * 8);
    }
}

__global__ void __launch_bounds__(128) attn_mma_kernel(
    const __nv_bfloat16* __restrict__ Qhi, const __nv_bfloat16* __restrict__ Qlo,
    const __nv_bfloat16* __restrict__ Khi, const __nv_bfloat16* __restrict__ Klo,
    const __nv_bfloat16* __restrict__ Vhi, const __nv_bfloat16* __restrict__ Vlo,
    __nv_bfloat16* __restrict__ Ohi, __nv_bfloat16* __restrict__ Olo)
{
    extern __shared__ char smraw[];
    const uint32_t smbQ = smem_u32(smraw);
    const uint32_t sb   = smbQ + 32768;     // single KV buffer
    const int tid = threadIdx.x, lane = tid & 31, warp = tid >> 5;  // 0..3
    const int sub = lane & 7, tl = lane >> 3;
    const int xorv = (sub >> 1) & 3;
    const int qaRow = warp * 16 + (tl & 1) * 8 + sub;   // 0..63
    const int qaK = tl >> 1;
    const int kbRow = (tl >> 1) * 8 + sub;
    const int kbK = tl & 1;
    const int vRow = lane & 15, vC = (lane >> 4) & 1;

    // LPT: heaviest q-tiles first
    const int qt = 15 - ((int)blockIdx.x >> 5);
    const int bh = blockIdx.x & 31;
    const int bq = bh >> 3, hd = bh & 7;
    const int qrow0 = bq * N_PATCH + qt * 64;

    // load Q (64 x 128, hi/lo)
#pragma unroll
    for (int i = 0; i < 16; i++) {
        int idx = tid + i * 128;
        int mat = idx >> 10, rem = idx & 1023;
        int r = rem >> 4, c = rem & 15;
        uint32_t so = (uint32_t)(mat * 16384 + (c >> 2) * 4096 + r * 64
                    + (((c & 3) ^ ((r >> 1) & 3)) * 16));
        cpasync16(smbQ + so, (mat ? Qlo : Qhi)
            + (size_t)(qrow0 + r) * D_MODEL + hd * 128 + c * 8);
    }
    att_load_kv(sb, Khi, Klo, Vhi, Vlo, bq * N_PATCH, hd, tid);
    cp_commit();
    cp_wait0();
    __syncthreads();

    float m0 = -1e30f, m1 = -1e30f, l0 = 0.f, l1 = 0.f;
    float O[16][4];
#pragma unroll
    for (int vt = 0; vt < 16; vt++)
#pragma unroll
        for (int e = 0; e < 4; e++) O[vt][e] = 0.f;

    const int nkv = qt + 1;
    for (int kt = 0; kt < nkv; kt++) {
        const int wrow = qt * 64 + warp * 16;
        {
            float s[8][4];
#pragma unroll
            for (int nt = 0; nt < 8; nt++)
#pragma unroll
                for (int e = 0; e < 4; e++) s[nt][e] = 0.f;

#pragma unroll
            for (int kk = 0; kk < 8; kk++) {
                uint32_t qh[4], ql[4];
                uint32_t qoff = (uint32_t)((kk >> 1) * 4096 + qaRow * 64
                              + ((((kk & 1) * 2 + qaK) ^ xorv) * 16));
                ldsm4(qh, smbQ + qoff);
                ldsm4(ql, smbQ + 16384 + qoff);
                uint32_t kh[4][4], kl[4][4];
#pragma unroll
                for (int n16 = 0; n16 < 4; n16++) {
                    uint32_t koff = (uint32_t)((kk >> 1) * 4096
                                  + (n16 * 16 + kbRow) * 64
                                  + ((((kk & 1) * 2 + kbK) ^ xorv) * 16));
                    ldsm4(kh[n16], sb + koff);
                    ldsm4(kl[n16], sb + 16384 + koff);
                }
#pragma unroll
                for (int n16 = 0; n16 < 4; n16++) {
                    mma16816(s[n16 * 2],     qh, kh[n16]);
                    mma16816(s[n16 * 2 + 1], qh, kh[n16] + 2);
                }
#pragma unroll
                for (int n16 = 0; n16 < 4; n16++) {
                    mma16816(s[n16 * 2],     qh, kl[n16]);
                    mma16816(s[n16 * 2 + 1], qh, kl[n16] + 2);
                }
#pragma unroll
                for (int n16 = 0; n16 < 4; n16++) {
                    mma16816(s[n16 * 2],     ql, kh[n16]);
                    mma16816(s[n16 * 2 + 1], ql, kh[n16] + 2);
                }
            }

            const int R0 = wrow + (lane >> 2), R1 = R0 + 8;
            const bool needMask = (kt * 64 + 63) > wrow;
#pragma unroll
            for (int nt = 0; nt < 8; nt++) {
                int C0 = kt * 64 + nt * 8 + (lane & 3) * 2;
                s[nt][0] *= ATTN_SCALE; s[nt][1] *= ATTN_SCALE;
                s[nt][2] *= ATTN_SCALE; s[nt][3] *= ATTN_SCALE;
                if (needMask) {
                    if (C0 > R0)     s[nt][0] = -1e30f;
                    if (C0 + 1 > R0) s[nt][1] = -1e30f;
                    if (C0 > R1)     s[nt][2] = -1e30f;
                    if (C0 + 1 > R1) s[nt][3] = -1e30f;
                }
            }

            float rm0 = -1e30f, rm1 = -1e30f;
#pragma unroll
            for (int nt = 0; nt < 8; nt++) {
                rm0 = fmaxf(rm0, fmaxf(s[nt][0], s[nt][1]));
                rm1 = fmaxf(rm1, fmaxf(s[nt][2], s[nt][3]));
            }
            rm0 = fmaxf(rm0, __shfl_xor_sync(0xffffffffu, rm0, 1));
            rm0 = fmaxf(rm0, __shfl_xor_sync(0xffffffffu, rm0, 2));
            rm1 = fmaxf(rm1, __shfl_xor_sync(0xffffffffu, rm1, 1));
            rm1 = fmaxf(rm1, __shfl_xor_sync(0xffffffffu, rm1, 2));

            float mn0 = fmaxf(m0, rm0), mn1 = fmaxf(m1, rm1);
            float a0 = __expf(m0 - mn0), a1 = __expf(m1 - mn1);
            m0 = mn0; m1 = mn1;

            float rs0 = 0.f, rs1 = 0.f;
#pragma unroll
            for (int nt = 0; nt < 8; nt++) {
                s[nt][0] = __expf(s[nt][0] - mn0);
                s[nt][1] = __expf(s[nt][1] - mn0);
                s[nt][2] = __expf(s[nt][2] - mn1);
                s[nt][3] = __expf(s[nt][3] - mn1);
                rs0 += s[nt][0] + s[nt][1];
                rs1 += s[nt][2] + s[nt][3];
            }
            rs0 += __shfl_xor_sync(0xffffffffu, rs0, 1);
            rs0 += __shfl_xor_sync(0xffffffffu, rs0, 2);
            rs1 += __shfl_xor_sync(0xffffffffu, rs1, 1);
            rs1 += __shfl_xor_sync(0xffffffffu, rs1, 2);
            l0 = l0 * a0 + rs0;
            l1 = l1 * a1 + rs1;

#pragma unroll
            for (int vt = 0; vt < 16; vt++) {
                O[vt][0] *= a0; O[vt][1] *= a0;
                O[vt][2] *= a1; O[vt][3] *= a1;
            }

#pragma unroll
            for (int kv16 = 0; kv16 < 4; kv16++) {
                uint32_t pH[4], pL[4];
                split2u(s[kv16*2][0],   s[kv16*2][1],   &pH[0], &pL[0]);
                split2u(s[kv16*2][2],   s[kv16*2][3],   &pH[1], &pL[1]);
                split2u(s[kv16*2+1][0], s[kv16*2+1][1], &pH[2], &pL[2]);
                split2u(s[kv16*2+1][2], s[kv16*2+1][3], &pH[3], &pL[3]);
#pragma unroll
                for (int vb = 0; vb < 2; vb++) {
                    uint32_t vh[4][4], vl[4][4];
#pragma unroll
                    for (int j = 0; j < 4; j++) {
                        int c = (vb * 4 + j) * 2 + vC;
                        int row = kv16 * 16 + vRow;
                        uint32_t swc = (uint32_t)((c & 8) | ((c & 7) ^ (row & 7)));
                        uint32_t voff = (uint32_t)(row * 256 + swc * 16);
                        ldsm4t(vh[j], sb + 32768 + voff);
                        ldsm4t(vl[j], sb + 49152 + voff);
                    }
#pragma unroll
                    for (int j = 0; j < 4; j++) {
                        int vn = vb * 4 + j;
                        mma16816(O[vn * 2],     pH, vh[j]);
                        mma16816(O[vn * 2 + 1], pH, vh[j] + 2);
                    }
#pragma unroll
                    for (int j = 0; j < 4; j++) {
                        int vn = vb * 4 + j;
                        mma16816(O[vn * 2],     pH, vl[j]);
                        mma16816(O[vn * 2 + 1], pH, vl[j] + 2);
                    }
#pragma unroll
                    for (int j = 0; j < 4; j++) {
                        int vn = vb * 4 + j;
                        mma16816(O[vn * 2],     pL, vh[j]);
                        mma16816(O[vn * 2 + 1], pL, vh[j] + 2);
                    }
                }
            }
        }

        if (kt + 1 < nkv) {
            __syncthreads();   // everyone done reading KV before overwrite
            att_load_kv(sb, Khi, Klo, Vhi, Vlo,
                        bq * N_PATCH + (kt + 1) * 64, hd, tid);
            cp_commit();
            cp_wait0();
            __syncthreads();
        }
    }

    const float inv0 = 1.f / l0, inv1 = 1.f / l1;
    const size_t r0 = (size_t)(qrow0 + warp * 16 + (lane >> 2)) * D_MODEL + hd * 128;
    const size_t r1 = r0 + 8 * D_MODEL;
#pragma unroll
    for (int vt = 0; vt < 16; vt++) {
        int c = vt * 8 + (lane & 3) * 2;
        __nv_bfloat162 h2, l2;
        split2(O[vt][0] * inv0, O[vt][1] * inv0, &h2, &l2);
        *(__nv_bfloat162*)(Ohi + r0 + c) = h2;
        *(__nv_bfloat162*)(Olo + r0 + c) = l2;
        split2(O[vt][2] * inv1, O[vt][3] * inv1, &h2, &l2);
        *(__nv_bfloat162*)(Ohi + r1 + c) = h2;
        *(__nv_bfloat162*)(Olo + r1 + c) = l2;
    }
}

// ======================= fp32 SGEMM (patch embedding) =======================
__global__ void __launch_bounds__(256) sgemm_kernel(
    const float* __restrict__ A, const float* __restrict__ W,
    __nv_bfloat16* __restrict__ Chi, __nv_bfloat16* __restrict__ Clo,
    int M, int N, int K)
{
    __shared__ float As[8 * 132];
    __shared__ float Bs[8 * 132];
    const int tid = threadIdx.x, tm = tid >> 4, tn = tid & 15;
    const int row0 = blockIdx.y * 128, col0 = blockIdx.x * 128;
    const int lrow = tid >> 1, lk = (tid & 1) * 4;
    const float* Ap = A + (size_t)(row0 + lrow) * K + lk;
    const float* Wp = W + (size_t)(col0 + lrow) * K + lk;

    float acc[8][8];
#pragma unroll
    for (int i = 0; i < 8; i++)
#pragma unroll
        for (int j = 0; j < 8; j++) acc[i][j] = 0.f;

    for (int kt = 0; kt < K; kt += 8) {
        float4 a4 = *(const float4*)(Ap + kt);
        float4 b4 = *(const float4*)(Wp + kt);
        __syncthreads();
        As[(lk+0)*132+lrow]=a4.x; As[(lk+1)*132+lrow]=a4.y;
        As[(lk+2)*132+lrow]=a4.z; As[(lk+3)*132+lrow]=a4.w;
        Bs[(lk+0)*132+lrow]=b4.x; Bs[(lk+1)*132+lrow]=b4.y;
        Bs[(lk+2)*132+lrow]=b4.z; Bs[(lk+3)*132+lrow]=b4.w;
        __syncthreads();
#pragma unroll
        for (int kk = 0; kk < 8; kk++) {
            float4 a0 = *(const float4*)&As[kk*132 + tm*4];
            float4 a1 = *(const float4*)&As[kk*132 + 64 + tm*4];
            float4 b0 = *(const float4*)&Bs[kk*132 + tn*4];
            float4 b1 = *(const float4*)&Bs[kk*132 + 64 + tn*4];
            float ar[8] = {a0.x,a0.y,a0.z,a0.w,a1.x,a1.y,a1.z,a1.w};
            float br[8] = {b0.x,b0.y,b0.z,b0.w,b1.x,b1.y,b1.z,b1.w};
#pragma unroll
            for (int i = 0; i < 8; i++)
#pragma unroll
                for (int j = 0; j < 8; j++)
                    acc[i][j] = fmaf(ar[i], br[j], acc[i][j]);
        }
    }

    float dv[8];
#pragma unroll
    for (int j = 0; j < 8; j++) {
        int c = col0 + ((j < 4) ? tn*4 + j : 64 + tn*4 + (j - 4));
        dv[j] = expf((float)(c & ~1) * PE_COEF);
    }
#pragma unroll
    for (int i = 0; i < 8; i++) {
        int r = row0 + ((i < 4) ? tm*4 + i : 64 + tm*4 + (i - 4));
        float pn = (float)(r & (N_PATCH - 1));
#pragma unroll
        for (int jb = 0; jb < 2; jb++) {
            int cb = col0 + (jb ? 64 + tn*4 : tn*4);
            float v[4];
#pragma unroll
            for (int qq = 0; qq < 4; qq++) {
                int j = jb*4 + qq;
                float ang = pn * dv[j];
                v[qq] = acc[i][j] + (((cb + qq) & 1) ? cosf(ang) : sinf(ang));
            }
            __nv_bfloat162 h, l;
            split2(v[0], v[1], &h, &l);
            *(__nv_bfloat162*)(Chi + (size_t)r * N + cb) = h;
            *(__nv_bfloat162*)(Clo + (size_t)r * N + cb) = l;
            split2(v[2], v[3], &h, &l);
            *(__nv_bfloat162*)(Chi + (size_t)r * N + cb + 2) = h;
            *(__nv_bfloat162*)(Clo + (size_t)r * N + cb + 2) = l;
        }
    }
}

// ======================= LayerNorm (128 thr, 4 rows/block) ==================
__global__ void __launch_bounds__(128) addln_kernel(
    const float* __restrict__ a,
    const float* __restrict__ g, const float* __restrict__ be,
    float* __restrict__ out,
    __nv_bfloat16* __restrict__ outHi, __nv_bfloat16* __restrict__ outLo)
{
    const int warp = threadIdx.x >> 5, lane = threadIdx.x & 31;
    const int row = blockIdx.x * 4 + warp;
    const float* ap = a + (size_t)row * D_MODEL;

    float x[32], sum = 0.f;
#pragma unroll
    for (int j = 0; j < 8; j++) {
        int col = j * 128 + lane * 4;
        float4 xv = *(const float4*)(ap + col);
        x[j*4+0]=xv.x; x[j*4+1]=xv.y; x[j*4+2]=xv.z; x[j*4+3]=xv.w;
        sum += xv.x + xv.y + xv.z + xv.w;
    }
#pragma unroll
    for (int o = 16; o > 0; o >>= 1) sum += __shfl_xor_sync(0xffffffffu, sum, o);
    const float mean = sum * (1.f / 1024.f);
    float vs = 0.f;
#pragma unroll
    for (int i = 0; i < 32; i++) { float d = x[i] - mean; vs = fmaf(d, d, vs); }
#pragma unroll
    for (int o = 16; o > 0; o >>= 1) vs += __shfl_xor_sync(0xffffffffu, vs, o);
    const float rstd = rsqrtf(vs * (1.f / 1024.f) + 1e-5f);

#pragma unroll
    for (int j = 0; j < 8; j++) {
        int col = j * 128 + lane * 4;
        float4 gv  = *(const float4*)(g + col);
        float4 bev = *(const float4*)(be + col);
        float4 ov;
        ov.x = (x[j*4+0]-mean)*rstd*gv.x + bev.x;
        ov.y = (x[j*4+1]-mean)*rstd*gv.y + bev.y;
        ov.z = (x[j*4+2]-mean)*rstd*gv.z + bev.z;
        ov.w = (x[j*4+3]-mean)*rstd*gv.w + bev.w;
        if (out) *(float4*)(out + (size_t)row * D_MODEL + col) = ov;
        __nv_bfloat162 h, l;
        split2(ov.x, ov.y, &h, &l);
        *(__nv_bfloat162*)(outHi + (size_t)row * D_MODEL + col) = h;
        *(__nv_bfloat162*)(outLo + (size_t)row * D_MODEL + col) = l;
        split2(ov.z, ov.w, &h, &l);
        *(__nv_bfloat162*)(outHi + (size_t)row * D_MODEL + col + 2) = h;
        *(__nv_bfloat162*)(outLo + (size_t)row * D_MODEL + col + 2) = l;
    }
}

#define GETSYM(var, sym) cudaGetSymbolAddress((void**)&var, sym)

extern "C" void kernel_launch(void* const* d_in, const int* in_sizes, int n_in,
                              void* d_out, int out_size)
{
    const float* x     = (const float*)d_in[0];
    const float* W_emb = (const float*)d_in[1];
    const float* Wq    = (const float*)d_in[2];
    const float* bq    = (const float*)d_in[3];
    const float* Wk    = (const float*)d_in[4];
    const float* bk    = (const float*)d_in[5];
    const float* Wv    = (const float*)d_in[6];
    const float* bv    = (const float*)d_in[7];
    const float* Wo    = (const float*)d_in[8];
    const float* bo    = (const float*)d_in[9];
    const float* Wc1   = (const float*)d_in[10];
    const float* bc1   = (const float*)d_in[11];
    const float* Wc2   = (const float*)d_in[12];
    const float* bc2   = (const float*)d_in[13];
    const float* g1    = (const float*)d_in[14];
    const float* be1   = (const float*)d_in[15];
    const float* g2    = (const float*)d_in[16];
    const float* be2   = (const float*)d_in[17];
    const float* gN    = (const float*)d_in[18];
    const float* beN   = (const float*)d_in[19];
    const float* Wp    = (const float*)d_in[20];
    const float* bp    = (const float*)d_in[21];

    float *h, *tmp;
    GETSYM(h, g_h); GETSYM(tmp, g_tmp);

    __nv_bfloat16 *hHi, *hLo, *qHi, *qLo, *kHi, *kLo, *vHi, *vLo,
                  *attHi, *attLo, *ffHi, *ffLo,
                  *wqkvH, *wqkvL, *woH, *woL, *w1H, *w1L, *w2H, *w2L, *wpH, *wpL;
    GETSYM(hHi, g_h_hi); GETSYM(hLo, g_h_lo);
    GETSYM(qHi, g_q_hi); GETSYM(qLo, g_q_lo);
    GETSYM(kHi, g_k_hi); GETSYM(kLo, g_k_lo);
    GETSYM(vHi, g_v_hi); GETSYM(vLo, g_v_lo);
    GETSYM(attHi, g_att_hi); GETSYM(attLo, g_att_lo);
    GETSYM(ffHi, g_ff_hi); GETSYM(ffLo, g_ff_lo);
    GETSYM(wqkvH, g_wqkv_hi); GETSYM(wqkvL, g_wqkv_lo);
    GETSYM(woH, g_wo_hi); GETSYM(woL, g_wo_lo);
    GETSYM(w1H, g_w1_hi); GETSYM(w1L, g_w1_lo);
    GETSYM(w2H, g_w2_hi); GETSYM(w2L, g_w2_lo);
    GETSYM(wpH, g_wp_hi); GETSYM(wpL, g_wp_lo);

    cudaFuncSetAttribute(attn_mma_kernel, cudaFuncAttributeMaxDynamicSharedMemorySize, ATT_SMEM);
    cudaFuncSetAttribute(gemm_mma_kernel<false>, cudaFuncAttributeMaxDynamicSharedMemorySize, GSMEM);
    cudaFuncSetAttribute(gemm_mma_kernel<true>, cudaFuncAttributeMaxDynamicSharedMemorySize, GSMEM);
    cudaFuncSetAttribute(gemm_qkv_kernel, cudaFuncAttributeMaxDynamicSharedMemorySize, GSMEM);

    dim3 blk(256);
    const dim3 gQKV (24, M_ROWS / 128);
    const dim3 gONE (D_MODEL / 128, M_ROWS / 128);
    const dim3 gFF1 (D_FF   / 128, M_ROWS / 128);
    const dim3 gPROJ(1, M_ROWS / 128);

    cvt3_kernel<<<dim3(WSZ / 4 / 256, 3), blk>>>(Wq, Wk, Wv, wqkvH, wqkvL);
    sgemm_kernel<<<dim3(8, 32), blk>>>(x, W_emb, hHi, hLo, M_ROWS, D_MODEL, P_LEN);
    cvt_pair_kernel<<<P_LEN * D_MODEL / 4 / 256, blk>>>(Wp, wpH, wpL, P_LEN * D_MODEL / 4);

    bool first = true;
    for (int i = 0; i < E_LAYERS; i++) {
        const size_t wo_ = (size_t)i * D_MODEL * D_MODEL;
        const size_t wf_ = (size_t)i * D_FF * D_MODEL;

        gemm_qkv_kernel<<<gQKV, blk, GSMEM>>>(hHi, hLo, wqkvH, wqkvL, i,
            bq, bk, bv, qHi, qLo, kHi, kLo, vHi, vLo);

        if (first) {
            cvt_pair_kernel<<<WSZ / 4 / 256, blk>>>(Wo,  woH, woL, WSZ / 4);
            cvt_pair_kernel<<<WFF / 4 / 256, blk>>>(Wc1, w1H, w1L, WFF / 4);
            cvt_pair_kernel<<<WFF / 4 / 256, blk>>>(Wc2, w2H, w2L, WFF / 4);
            first = false;
        }

        attn_mma_kernel<<<512, 128, ATT_SMEM>>>(qHi, qLo, kHi, kLo, vHi, vLo,
                                                attHi, attLo);

        // tmp = (hHi+hLo) + att @ Wo^T + bo
        gemm_mma_kernel<false><<<gONE, blk, GSMEM>>>(attHi, attLo, woH + wo_,
            woL + wo_, bo + i * D_MODEL, hHi, hLo, tmp, nullptr, nullptr,
            D_MODEL, D_MODEL, D_MODEL, 0);
        addln_kernel<<<1024, 128>>>(tmp, g1 + i * D_MODEL, be1 + i * D_MODEL,
                                    nullptr, hHi, hLo);

        gemm_mma_kernel<false><<<gFF1, blk, GSMEM>>>(hHi, hLo, w1H + wf_,
            w1L + wf_, bc1 + i * D_FF, nullptr, nullptr, nullptr, ffHi, ffLo,
            D_MODEL, D_FF, D_FF, 1);
        gemm_mma_kernel<false><<<gONE, blk, GSMEM>>>(ffHi, ffLo, w2H + wf_,
            w2L + wf_, bc2 + i * D_MODEL, hHi, hLo, tmp, nullptr, nullptr,
            D_FF, D_MODEL, D_MODEL, 0);
        addln_kernel<<<1024, 128>>>(tmp, g2 + i * D_MODEL, be2 + i * D_MODEL,
                                    (i == E_LAYERS - 1) ? h : nullptr, hHi, hLo);
    }

    addln_kernel<<<1024, 128>>>(h, gN, beN, nullptr, qHi, qLo);
    gemm_mma_kernel<true><<<gPROJ, blk, GSMEM>>>(qHi, qLo, wpH, wpL, bp,
        nullptr, nullptr, (float*)d_out, nullptr, nullptr,
        D_MODEL, P_LEN, P_LEN, 0);
}